// round 13
// baseline (speedup 1.0000x reference)
#include <cuda_runtime.h>

// Problem geometry
#define NB   2
#define NI   256
#define NJ   256
#define NK   64
#define CVOL (NI*NJ*NK)                       // 4,194,304 per (batch,channel)
#define NPIX ((double)NB*CVOL)                // 8,388,608
#define NCELL ((double)NB*255.0*255.0*63.0)   // cells
#define GRID 8192

__device__ double g_acc[4];   // zero at module load; finalize resets after use

// ---------------- packed fp32x2 helpers (sm_103a FFMA2 path) ----------------
typedef unsigned long long u64;

__device__ __forceinline__ u64 pk2(float lo, float hi) {
    u64 r; asm("mov.b64 %0, {%1, %2};" : "=l"(r) : "f"(lo), "f"(hi)); return r;
}
__device__ __forceinline__ void upk2(u64 v, float& a, float& b) {
    asm("mov.b64 {%0, %1}, %2;" : "=f"(a), "=f"(b) : "l"(v));
}
__device__ __forceinline__ u64 add2(u64 a, u64 b) {
    u64 r; asm("add.rn.f32x2 %0, %1, %2;" : "=l"(r) : "l"(a), "l"(b)); return r;
}
__device__ __forceinline__ u64 sub2(u64 a, u64 b) {
    u64 r; asm("sub.rn.f32x2 %0, %1, %2;" : "=l"(r) : "l"(a), "l"(b)); return r;
}
__device__ __forceinline__ u64 mul2(u64 a, u64 b) {
    u64 r; asm("mul.rn.f32x2 %0, %1, %2;" : "=l"(r) : "l"(a), "l"(b)); return r;
}
__device__ __forceinline__ u64 fma2(u64 a, u64 b, u64 c) {
    u64 r; asm("fma.rn.f32x2 %0, %1, %2, %3;" : "=l"(r) : "l"(a), "l"(b), "l"(c)); return r;
}

__global__ void __launch_bounds__(256, 2)
loss_kernel(const float* __restrict__ O, const float* __restrict__ T)
{
    const int tid  = blockIdx.x * 256 + threadIdx.x;
    const int lane = threadIdx.x & 31;
    const int hl   = lane & 15;          // lane within half-warp (k block)
    const int half = lane >> 4;          // batch index b
    const int w    = tid >> 5;           // 65536 warps = 256*256 (i,j) rows
    const int i    = w >> 8;
    const int j    = w & 255;

    const int base = (w << 6) + (hl << 2);     // (i*256+j)*64 + 4*hl
    const float* __restrict__ Obl = O + half * (3 * CVOL);
    const float* __restrict__ Tbl = T + half * (4 * CVOL);

    // clamped corner offsets (warp-uniform; contribution gated below)
    const int io = (i < NI - 1) ? (NJ * NK) : 0;
    const int jo = (j < NJ - 1) ? NK : 0;
    const int off0 = 0, off1 = jo, off2 = io, off3 = io + jo;

    // ---- front-batched loads: 19 x LDG.128 per thread (serves 2 rows/warp) ----
    float4 CBX[4], CBY[4], CBZ[4], CZ[4];
    CBX[0] = *(const float4*)(Obl + base + off0);
    CBX[1] = *(const float4*)(Obl + base + off1);
    CBX[2] = *(const float4*)(Obl + base + off2);
    CBX[3] = *(const float4*)(Obl + base + off3);
    CBY[0] = *(const float4*)(Obl + CVOL + base + off0);
    CBY[1] = *(const float4*)(Obl + CVOL + base + off1);
    CBY[2] = *(const float4*)(Obl + CVOL + base + off2);
    CBY[3] = *(const float4*)(Obl + CVOL + base + off3);
    CBZ[0] = *(const float4*)(Obl + 2*CVOL + base + off0);
    CBZ[1] = *(const float4*)(Obl + 2*CVOL + base + off1);
    CBZ[2] = *(const float4*)(Obl + 2*CVOL + base + off2);
    CBZ[3] = *(const float4*)(Obl + 2*CVOL + base + off3);
    CZ[0]  = *(const float4*)(Tbl + 3*CVOL + base + off0);
    CZ[1]  = *(const float4*)(Tbl + 3*CVOL + base + off1);
    CZ[2]  = *(const float4*)(Tbl + 3*CVOL + base + off2);
    CZ[3]  = *(const float4*)(Tbl + 3*CVOL + base + off3);
    const float4 TXv = *(const float4*)(Tbl + base);
    const float4 TYv = *(const float4*)(Tbl + CVOL + base);
    const float4 TZv = *(const float4*)(Tbl + 2*CVOL + base);

    // ---- k+4 halo: shuffled .x from lane+1 (cross-half garbage gated) ----
    const unsigned FULL = 0xffffffffu;
    float SBX[4], SBY[4], SBZ[4], SZ[4];
    #pragma unroll
    for (int c = 0; c < 4; c++) {
        SBX[c] = __shfl_down_sync(FULL, CBX[c].x, 1);
        SBY[c] = __shfl_down_sync(FULL, CBY[c].x, 1);
        SBZ[c] = __shfl_down_sync(FULL, CBZ[c].x, 1);
        SZ[c]  = __shfl_down_sync(FULL, CZ[c].x, 1);
    }

    const u64 EPS2 = pk2(1e-10f, 1e-10f);

    float s_bxy = 0.f, s_bz = 0.f, s_par = 0.f, s_div = 0.f;

    // ================= element-wise losses: 4 k-values = 2 packed passes ====
    #pragma unroll
    for (int e = 0; e < 2; e++) {
        const u64 bxp = e ? pk2(CBX[0].z, CBX[0].w) : pk2(CBX[0].x, CBX[0].y);
        const u64 byp = e ? pk2(CBY[0].z, CBY[0].w) : pk2(CBY[0].x, CBY[0].y);
        const u64 bzp = e ? pk2(CBZ[0].z, CBZ[0].w) : pk2(CBZ[0].x, CBZ[0].y);
        const u64 bxt = e ? pk2(TXv.z, TXv.w) : pk2(TXv.x, TXv.y);
        const u64 byt = e ? pk2(TYv.z, TYv.w) : pk2(TYv.x, TYv.y);
        const u64 bzt = e ? pk2(TZv.z, TZv.w) : pk2(TZv.x, TZv.y);

        const u64 bxt2 = mul2(bxt, bxt);
        const u64 byt2 = mul2(byt, byt);
        const u64 bzt2 = mul2(bzt, bzt);
        const u64 st   = add2(bxt2, byt2);

        const u64 t   = sub2(fma2(bxp, bxp, mul2(byp, byp)), st);
        const u64 t2  = mul2(t, t);
        const u64 dn1 = add2(st, EPS2);

        const u64 dz  = sub2(bzp, bzt);
        const u64 dz2 = mul2(dz, dz);
        const u64 dz4 = mul2(dz2, dz2);
        const u64 dn2 = add2(bzt2, EPS2);

        const u64 cr  = sub2(mul2(bxp, byt), mul2(byp, bxt));
        const u64 cr2 = mul2(cr, cr);
        const u64 dn3 = add2(add2(st, bzt2), EPS2);

        float na, nb, da, db;
        upk2(t2, na, nb);  upk2(dn1, da, db);
        s_bxy += __fdividef(na*db + nb*da, da*db);
        upk2(dz4, na, nb); upk2(dn2, da, db);
        s_bz  += __fdividef(na*db + nb*da, da*db);
        upk2(cr2, na, nb); upk2(dn3, da, db);
        s_par += __fdividef(na*db + nb*da, da*db);
    }

    // ========== divergence: 2 packed passes, CHANNEL-SEQUENTIAL (low regs) ==
    if (i < NI - 1 && j < NJ - 1) {            // warp-uniform branch
        const u64 C0125 = pk2(0.0125f, 0.0125f);        // 0.125 * 0.1
        const u64 C0025 = pk2(0.0025f, 0.0025f);        // 0.25 * 0.1 * 0.1
        const u64 C6    = pk2(0.1f/6.f, 0.1f/6.f);      // DX/6 = DY/6
        const u64 C8    = pk2(0.125f, 0.125f);

        #pragma unroll
        for (int p = 0; p < 2; p++) {
            // z corner packs for cells (4hl+2p, 4hl+2p+1)
            u64 za[4], zb[4];
            #pragma unroll
            for (int c = 0; c < 4; c++) {
                za[c] = p ? pk2(CZ[c].z, CZ[c].w) : pk2(CZ[c].x, CZ[c].y);
                zb[c] = p ? pk2(CZ[c].w, SZ[c])   : pk2(CZ[c].y, CZ[c].z);
            }

            u64 num = pk2(0.f, 0.f);
            u64 den = EPS2;

            // ---- channel bx ----
            {
                u64 a[4], bq[4];
                #pragma unroll
                for (int c = 0; c < 4; c++) {
                    a[c]  = p ? pk2(CBX[c].z, CBX[c].w) : pk2(CBX[c].x, CBX[c].y);
                    bq[c] = p ? pk2(CBX[c].w, SBX[c])   : pk2(CBX[c].y, CBX[c].z);
                }
                const u64 sxp = add2(add2(a[2], a[3]), add2(bq[2], bq[3]));
                const u64 sxm = add2(add2(a[0], a[1]), add2(bq[0], bq[1]));
                const u64 dxp = add2(sub2(zb[2], za[2]), sub2(zb[3], za[3]));
                const u64 dxm = add2(sub2(zb[0], za[0]), sub2(zb[1], za[1]));
                const u64 termx = sub2(mul2(sxp, dxp), mul2(sxm, dxm));

                const u64 tx1 = mul2(add2(add2(bq[0], bq[2]), bq[3]), sub2(zb[0], zb[2]));
                const u64 tx2 = mul2(add2(add2(bq[1], bq[3]), bq[2]), sub2(zb[1], zb[3]));
                const u64 tx3 = mul2(add2(add2(a[0], a[2]), a[3]), sub2(za[0], za[2]));
                const u64 tx4 = mul2(add2(add2(a[1], a[3]), a[2]), sub2(za[1], za[3]));
                const u64 trix = sub2(add2(tx1, tx2), add2(tx3, tx4));

                num = fma2(C0125, termx, fma2(C6, trix, num));
                const u64 cs = add2(add2(add2(a[0], a[1]), add2(a[2], a[3])),
                                    add2(add2(bq[0], bq[1]), add2(bq[2], bq[3])));
                const u64 cx = mul2(C8, cs);
                den = fma2(cx, cx, den);
            }

            // ---- channel by ----
            {
                u64 a[4], bq[4];
                #pragma unroll
                for (int c = 0; c < 4; c++) {
                    a[c]  = p ? pk2(CBY[c].z, CBY[c].w) : pk2(CBY[c].x, CBY[c].y);
                    bq[c] = p ? pk2(CBY[c].w, SBY[c])   : pk2(CBY[c].y, CBY[c].z);
                }
                const u64 syp = add2(add2(a[1], a[3]), add2(bq[1], bq[3]));
                const u64 sym = add2(add2(a[0], a[2]), add2(bq[0], bq[2]));
                const u64 dyp = add2(sub2(zb[1], za[1]), sub2(zb[3], za[3]));
                const u64 dym = add2(sub2(zb[0], za[0]), sub2(zb[2], za[2]));
                const u64 termy = sub2(mul2(syp, dyp), mul2(sym, dym));

                const u64 ty1 = mul2(add2(add2(bq[2], bq[3]), bq[1]), sub2(zb[2], zb[3]));
                const u64 ty2 = mul2(add2(add2(bq[0], bq[1]), bq[3]), sub2(zb[0], zb[1]));
                const u64 ty3 = mul2(add2(add2(a[2], a[3]), a[1]), sub2(za[2], za[3]));
                const u64 ty4 = mul2(add2(add2(a[0], a[1]), a[3]), sub2(za[0], za[1]));
                const u64 triy = sub2(add2(ty1, ty2), add2(ty3, ty4));

                num = fma2(C0125, termy, fma2(C6, triy, num));
                const u64 cs = add2(add2(add2(a[0], a[1]), add2(a[2], a[3])),
                                    add2(add2(bq[0], bq[1]), add2(bq[2], bq[3])));
                const u64 cy = mul2(C8, cs);
                den = fma2(cy, cy, den);
            }

            // ---- channel bz ----
            {
                u64 a[4], bq[4];
                #pragma unroll
                for (int c = 0; c < 4; c++) {
                    a[c]  = p ? pk2(CBZ[c].z, CBZ[c].w) : pk2(CBZ[c].x, CBZ[c].y);
                    bq[c] = p ? pk2(CBZ[c].w, SBZ[c])   : pk2(CBZ[c].y, CBZ[c].z);
                }
                const u64 sa = add2(add2(a[0], a[1]), add2(a[2], a[3]));
                const u64 sb = add2(add2(bq[0], bq[1]), add2(bq[2], bq[3]));
                const u64 termz = sub2(sb, sa);
                num = fma2(C0025, termz, num);
                const u64 cz = mul2(C8, add2(sa, sb));
                den = fma2(cz, cz, den);
            }

            float n0, n1, d0, d1;
            upk2(mul2(num, num), n0, n1);
            upk2(den, d0, d1);
            if (p == 1 && hl == 15) { n1 = 0.f; d1 = 1.0f; }  // cell k=63 invalid
            s_div += __fdividef(n0*d1 + n1*d0, d0*d1);
        }
    }

    // ================= reduction (packed pairs) ============================
    u64 p1 = pk2(s_bxy, s_bz);
    u64 p2 = pk2(s_par, s_div);
    #pragma unroll
    for (int o = 16; o; o >>= 1) {
        p1 = add2(p1, __shfl_down_sync(FULL, p1, o));
        p2 = add2(p2, __shfl_down_sync(FULL, p2, o));
    }
    __shared__ float sh[4][8];
    const int wb = threadIdx.x >> 5;
    if (lane == 0) {
        float a, b2, c, d;
        upk2(p1, a, b2); upk2(p2, c, d);
        sh[0][wb] = a; sh[1][wb] = b2; sh[2][wb] = c; sh[3][wb] = d;
    }
    __syncthreads();
    if (threadIdx.x < 4) {
        float s = 0.f;
        #pragma unroll
        for (int q = 0; q < 8; q++) s += sh[threadIdx.x][q];
        atomicAdd(&g_acc[threadIdx.x], (double)s);
    }
}

__global__ void finalize_kernel(float* __restrict__ out)
{
    const double lb = g_acc[0] / NPIX + g_acc[1] / NPIX;
    const double lp = g_acc[2] / NPIX;
    out[0] = (float)(1000.0 * lb + 1000.0 * lp);
    out[1] = (float)(100.0 * (g_acc[3] / NCELL) * 1.0e4);  // / DX^2 / DY^2
    // reset for the next graph replay (g_acc starts zero at module load)
    g_acc[0] = 0.0; g_acc[1] = 0.0; g_acc[2] = 0.0; g_acc[3] = 0.0;
}

extern "C" void kernel_launch(void* const* d_in, const int* in_sizes, int n_in,
                              void* d_out, int out_size)
{
    const float* outputs = (const float*)d_in[0];
    const float* targets = (const float*)d_in[1];
    if (n_in >= 2 && in_sizes[0] == 4 * NB * CVOL && in_sizes[1] == 3 * NB * CVOL) {
        const float* t = outputs; outputs = targets; targets = t;
    }
    loss_kernel<<<GRID, 256>>>(outputs, targets);
    finalize_kernel<<<1, 1>>>((float*)d_out);
}